// round 9
// baseline (speedup 1.0000x reference)
#include <cuda_runtime.h>
#include <cuda_fp16.h>
#include <cstdint>

// Fourier-KAN: out[b,o] = bias[o] + sum_{i,k} cos(k x[b,i]) c0[i,o,k-1] + sin(k x) c1[i,o,k-1]
// B=32768, I=512, O=64, G=8  ->  GEMM M=32768, N=64, K=8192, fp16 features on the fly.
// R9: register-A (proven in R8) + proper warp budget.
//   MCTA=128, 256 threads (8 warps), warp tile 32x32 (4 m-warps x 2 n-warps),
//   grid=256 -> ~14 warps/SM. B via 3-stage cp.async ring; B-LDSM halved per warp.
//   Tensor floor is ~57us chip-wide; everything else is sized to hide under it.

#define NB 32768
#define NI 512
#define NO 64
#define NG 8
#define KTOT 8192
#define MCTA 128
#define KC 64              // 4 i-values * 16 features
#define NCHUNK 128
#define NTHREADS 256
#define BSTAGES 3
#define BBYTES (64 * 128)  // one B chunk: 64 rows x 128B

// repacked coeffs: Wt[o][k], k = i*16 + t*8 + g; t=0: cos freq g+1, t=1: sin freq g+1
__device__ __half g_Wt[NO * KTOT];

// ---------------- helpers ----------------
__device__ __forceinline__ uint32_t smem_u32(const void* p) {
    uint32_t a;
    asm("{ .reg .u64 t; cvta.to.shared.u64 t, %1; cvt.u32.u64 %0, t; }" : "=r"(a) : "l"(p));
    return a;
}

#define SW128(o) ((o) ^ (((o) >> 3) & 0x70))

#define LDSM_X4(r0, r1, r2, r3, addr) \
    asm volatile("ldmatrix.sync.aligned.m8n8.x4.shared.b16 {%0,%1,%2,%3}, [%4];" \
                 : "=r"(r0), "=r"(r1), "=r"(r2), "=r"(r3) : "r"(addr))

#define CP_ASYNC16(dst, src) \
    asm volatile("cp.async.ca.shared.global [%0], [%1], 16;" \
                 :: "r"(dst), "l"(src) : "memory")
#define CP_COMMIT() asm volatile("cp.async.commit_group;" ::: "memory")
#define CP_WAIT1()  asm volatile("cp.async.wait_group 1;" ::: "memory")

__device__ __forceinline__ void mma16816(float* d, const uint32_t* a,
                                         uint32_t b0, uint32_t b1) {
    asm volatile(
        "mma.sync.aligned.m16n8k16.row.col.f32.f16.f16.f32 "
        "{%0,%1,%2,%3}, {%4,%5,%6,%7}, {%8,%9}, {%0,%1,%2,%3};"
        : "+f"(d[0]), "+f"(d[1]), "+f"(d[2]), "+f"(d[3])
        : "r"(a[0]), "r"(a[1]), "r"(a[2]), "r"(a[3]), "r"(b0), "r"(b1));
}

// 4x4 transpose across a lane-quad: v[s] (lane j) -> v'[s] = old v[j] of lane s.
__device__ __forceinline__ void quad_transpose4(uint32_t v[4], int j) {
    const bool b0 = (j & 1) != 0;
    const bool b1 = (j & 2) != 0;
    uint32_t t0 = b0 ? v[0] : v[1];
    uint32_t t1 = b0 ? v[2] : v[3];
    t0 = __shfl_xor_sync(0xffffffffu, t0, 1);
    t1 = __shfl_xor_sync(0xffffffffu, t1, 1);
    if (b0) { v[0] = t0; v[2] = t1; } else { v[1] = t0; v[3] = t1; }
    uint32_t u0 = b1 ? v[0] : v[2];
    uint32_t u1 = b1 ? v[1] : v[3];
    u0 = __shfl_xor_sync(0xffffffffu, u0, 2);
    u1 = __shfl_xor_sync(0xffffffffu, u1, 2);
    if (b1) { v[0] = u0; v[1] = u1; } else { v[2] = u0; v[3] = u1; }
}

// ---------------- prep: repack coeffs (2,I,O,G) f32 -> Wt[o][k] fp16 ----------------
__global__ void fkan_prep(const float* __restrict__ cf) {
    int idx = blockIdx.x * blockDim.x + threadIdx.x;
    if (idx >= NO * KTOT) return;
    int o = idx >> 13;
    int k = idx & (KTOT - 1);
    int i = k >> 4;
    int f = k & 15;
    int t = f >> 3;               // 0 = cos, 1 = sin
    int g = f & 7;                // freq-1
    float v = cf[(((t * NI) + i) * NO + o) * NG + g];
    g_Wt[o * KTOT + k] = __float2half(v);
}

// ---------------- main fused kernel ----------------
__global__ void __launch_bounds__(NTHREADS, 2)
fkan_main(const float* __restrict__ x, const float* __restrict__ bias,
          float* __restrict__ out) {
    __shared__ __align__(1024) char smem[BSTAGES * BBYTES];
    const uint32_t sbase = smem_u32(smem);

    const int tid = threadIdx.x;
    const int w = tid >> 5;
    const int lane = tid & 31;
    const int mw = w & 3;               // m-warp: rows mw*32..+31
    const int nh = w >> 2;              // n-warp: cols nh*32..+31
    const int q = lane >> 2;
    const int j = lane & 3;

    // ---- x pointers: this lane computes i = 4c + j for 4 row-slots ----
    const int ctaRow = blockIdx.x * MCTA;
    const float* xp[4];
    #pragma unroll
    for (int u = 0; u < 4; ++u) {
        const int roff = (u & 1) * 8 + (u >> 1) * 16;   // q, q+8, q+16, q+24
        xp[u] = x + (size_t)(ctaRow + mw * 32 + q + roff) * NI + j;
    }

    // ---- B loader: thread t -> row t>>2, 2 x 16B units at (t&3)*2 ----
    const int bo = tid >> 2;                 // 0..63
    const int buh = (tid & 3) << 1;          // 0,2,4,6
    const __half* wsrc = g_Wt + bo * KTOT + buh * 8;
    uint32_t b_st[2];
    #pragma unroll
    for (int u = 0; u < 2; ++u)
        b_st[u] = SW128((uint32_t)(bo * 128 + (buh + u) * 16));

    // ---- B ldmatrix lane addrs: 2 col-tiles for this n-warp ----
    const uint32_t bl = (uint32_t)((lane & 7) + ((lane >> 4) << 3));
    const uint32_t bbo = (uint32_t)(((lane >> 3) & 1) << 4);
    uint32_t b_ls[2];
    #pragma unroll
    for (int t = 0; t < 2; ++t)
        b_ls[t] = SW128((uint32_t)((nh * 32 + t * 16 + bl) * 128 + bbo));

    float acc[2][4][4];
    #pragma unroll
    for (int mi = 0; mi < 2; ++mi)
        #pragma unroll
        for (int jj = 0; jj < 4; ++jj)
            #pragma unroll
            for (int qq = 0; qq < 4; ++qq) acc[mi][jj][qq] = 0.0f;

    auto issueB = [&](int c) {
        const uint32_t d0 = sbase + (uint32_t)(c % BSTAGES) * BBYTES;
        const __half* s = wsrc + (size_t)c * KC;
        #pragma unroll
        for (int u = 0; u < 2; ++u)
            CP_ASYNC16(d0 + b_st[u], s + u * 8);
    };

    // ---- prologue ----
    issueB(0); CP_COMMIT();
    issueB(1); CP_COMMIT();
    float xv[4];
    #pragma unroll
    for (int u = 0; u < 4; ++u) xv[u] = *(xp[u]);
    CP_WAIT1();          // chunk-0 B done
    __syncthreads();

    #pragma unroll 1
    for (int c = 0; c < NCHUNK; ++c) {
        // kick B for c+2
        if (c + 2 < NCHUNK) issueB(c + 2);
        CP_COMMIT();

        // prefetch x for c+1 (clamped)
        const int cp = (c + 1 < NCHUNK) ? c + 1 : NCHUNK - 1;
        float xn[4];
        #pragma unroll
        for (int u = 0; u < 4; ++u) xn[u] = *(xp[u] + cp * 4);

        // ---- chains + quad transpose -> A fragments in registers ----
        uint32_t TC[4][4], TS[4][4];
        #pragma unroll
        for (int u = 0; u < 4; ++u) {
            float s1, c1;
            __sincosf(xv[u], &s1, &c1);
            const float t2 = c1 + c1;
            float ca = c1, sa = s1;
            float cb = fmaf(t2, c1, -1.0f);
            float sb = t2 * s1;
            __half2 h;
            h = __floats2half2_rn(ca, cb); TC[u][0] = *(uint32_t*)&h;
            h = __floats2half2_rn(sa, sb); TS[u][0] = *(uint32_t*)&h;
            #pragma unroll
            for (int p = 1; p < 4; ++p) {
                const float c_odd = fmaf(t2, cb, -ca);
                const float s_odd = fmaf(t2, sb, -sa);
                const float c_evn = fmaf(t2, c_odd, -cb);
                const float s_evn = fmaf(t2, s_odd, -sb);
                ca = c_odd; sa = s_odd; cb = c_evn; sb = s_evn;
                h = __floats2half2_rn(c_odd, c_evn); TC[u][p] = *(uint32_t*)&h;
                h = __floats2half2_rn(s_odd, s_evn); TS[u][p] = *(uint32_t*)&h;
            }
            quad_transpose4(TC[u], j);
            quad_transpose4(TS[u], j);
        }

        // ---- mma over 4 k16-steps from B smem + register A ----
        const uint32_t bB = sbase + (uint32_t)(c % BSTAGES) * BBYTES;
        #pragma unroll
        for (int ks = 0; ks < 4; ++ks) {
            const uint32_t kx = (uint32_t)(ks << 5);
            uint32_t b[8];
            #pragma unroll
            for (int t = 0; t < 2; ++t)
                LDSM_X4(b[4 * t], b[4 * t + 1], b[4 * t + 2], b[4 * t + 3],
                        bB + (b_ls[t] ^ kx));
            const uint32_t a0[4] = {TC[0][ks], TC[1][ks], TS[0][ks], TS[1][ks]};
            const uint32_t a1[4] = {TC[2][ks], TC[3][ks], TS[2][ks], TS[3][ks]};
            #pragma unroll
            for (int jj = 0; jj < 4; ++jj) {
                const uint32_t* bp = b + 4 * (jj >> 1);
                const int hi = (jj & 1) << 1;
                mma16816(acc[0][jj], a0, bp[hi], bp[hi + 1]);
                mma16816(acc[1][jj], a1, bp[hi], bp[hi + 1]);
            }
        }

        #pragma unroll
        for (int u = 0; u < 4; ++u) xv[u] = xn[u];
        CP_WAIT1();          // B for c+1 complete (this thread)
        __syncthreads();     // publish across threads; all reads of buf c done
    }

    // ---- epilogue: acc (+bias) -> out ----
    const int gr = lane >> 2;
    const int gc = (lane & 3) << 1;
    #pragma unroll
    for (int mi = 0; mi < 2; ++mi) {
        const int row0 = ctaRow + mw * 32 + mi * 16 + gr;
        #pragma unroll
        for (int jj = 0; jj < 4; ++jj) {
            const int col = nh * 32 + jj * 8 + gc;
            float2 bb2 = *(const float2*)(bias + col);
            float2 v0, v1;
            v0.x = acc[mi][jj][0] + bb2.x; v0.y = acc[mi][jj][1] + bb2.y;
            v1.x = acc[mi][jj][2] + bb2.x; v1.y = acc[mi][jj][3] + bb2.y;
            *(float2*)(out + (size_t)row0 * NO + col) = v0;
            *(float2*)(out + (size_t)(row0 + 8) * NO + col) = v1;
        }
    }
}

// ---------------- launch ----------------
extern "C" void kernel_launch(void* const* d_in, const int* in_sizes, int n_in,
                              void* d_out, int out_size) {
    const float* x    = (const float*)d_in[0];
    const float* cf   = (const float*)d_in[1];
    const float* bias = (const float*)d_in[2];
    float* out        = (float*)d_out;

    fkan_prep<<<(NO * KTOT + 255) / 256, 256>>>(cf);
    fkan_main<<<NB / MCTA, NTHREADS>>>(x, bias, out);
}

// round 10
// speedup vs baseline: 1.5354x; 1.5354x over previous
#include <cuda_runtime.h>
#include <cuda_fp16.h>
#include <cstdint>

// Fourier-KAN: out[b,o] = bias[o] + sum_{i,k} cos(k x[b,i]) c0[i,o,k-1] + sin(k x) c1[i,o,k-1]
// B=32768, I=512, O=64, G=8  ->  GEMM M=32768, N=64, K=8192, fp16 features on the fly.
// R10: R6's warp-specialized producer/consumer pipeline (best measured per-SM dynamics),
// retiled to MCTA=224 (7 consumer + 7 producer warps, 448 threads), grid=147 so ALL
// 148 SMs get work (R6 left 20 SMs idle). 4-stage mbarrier ring. Tail CTA predicated.

#define NB 32768
#define NI 512
#define NO 64
#define NG 8
#define KTOT 8192
#define MCTA 224
#define KC 64              // K per chunk = 4 i-values * 16 features
#define NCHUNK 128
#define NTHREADS 448
#define NGRID ((NB + MCTA - 1) / MCTA)     // 147
#define STAGES 4

#define ABYTES (MCTA * 128)        // 28672
#define BBYTES (64 * 128)          // 8192
#define BUFSZ  (ABYTES + BBYTES)   // 36864
#define SMEM_BUF0 1024
#define SMEM_TOTAL (SMEM_BUF0 + STAGES * BUFSZ)   // 148480

// repacked coeffs: Wt[o][k], k = i*16 + f; f<8: cos freq f+1, f>=8: sin freq f-7
__device__ __half g_Wt[NO * KTOT];

// ---------------- helpers ----------------
__device__ __forceinline__ uint32_t smem_u32(const void* p) {
    uint32_t a;
    asm("{ .reg .u64 t; cvta.to.shared.u64 t, %1; cvt.u32.u64 %0, t; }" : "=r"(a) : "l"(p));
    return a;
}

#define SW128(o) ((o) ^ (((o) >> 3) & 0x70))

#define LDSM_X4(r0, r1, r2, r3, addr) \
    asm volatile("ldmatrix.sync.aligned.m8n8.x4.shared.b16 {%0,%1,%2,%3}, [%4];" \
                 : "=r"(r0), "=r"(r1), "=r"(r2), "=r"(r3) : "r"(addr))

#define CP_ASYNC16(dst, src) \
    asm volatile("cp.async.ca.shared.global [%0], [%1], 16;" \
                 :: "r"(dst), "l"(src) : "memory")
#define CP_COMMIT() asm volatile("cp.async.commit_group;" ::: "memory")
#define CP_WAIT0()  asm volatile("cp.async.wait_group 0;" ::: "memory")

#define MBAR_INIT(a, c) \
    asm volatile("mbarrier.init.shared.b64 [%0], %1;" :: "r"((uint32_t)(a)), "r"((uint32_t)(c)) : "memory")
#define MBAR_ARRIVE(a) \
    asm volatile("mbarrier.arrive.shared.b64 _, [%0];" :: "r"((uint32_t)(a)) : "memory")

#define MBAR_WAIT_PARITY(addr, parity) do {                                        \
    uint32_t _mbar = (uint32_t)(addr);                                             \
    uint32_t _par = (uint32_t)(parity);                                            \
    uint32_t _done;                                                                \
    asm volatile("{\n\t.reg .pred p;\n\t"                                          \
        "mbarrier.try_wait.parity.acquire.cta.shared::cta.b64 p, [%1], %2;\n\t"    \
        "selp.b32 %0, 1, 0, p;\n\t}"                                               \
        : "=r"(_done) : "r"(_mbar), "r"(_par) : "memory");                         \
    if (!_done) {                                                                  \
        asm volatile("{\n\t.reg .pred P1;\n\t"                                     \
            "WAIT_LOOP_%=:\n\t"                                                    \
            "mbarrier.try_wait.parity.acquire.cta.shared::cta.b64 P1, [%0], %1, 0x989680;\n\t" \
            "@P1 bra.uni WAIT_DONE_%=;\n\t"                                        \
            "bra.uni WAIT_LOOP_%=;\n\t"                                            \
            "WAIT_DONE_%=:\n\t}"                                                   \
            :: "r"(_mbar), "r"(_par) : "memory");                                  \
    }                                                                              \
} while (0)

__device__ __forceinline__ void mma16816(float* d, const uint32_t* a,
                                         uint32_t b0, uint32_t b1) {
    asm volatile(
        "mma.sync.aligned.m16n8k16.row.col.f32.f16.f16.f32 "
        "{%0,%1,%2,%3}, {%4,%5,%6,%7}, {%8,%9}, {%0,%1,%2,%3};"
        : "+f"(d[0]), "+f"(d[1]), "+f"(d[2]), "+f"(d[3])
        : "r"(a[0]), "r"(a[1]), "r"(a[2]), "r"(a[3]), "r"(b0), "r"(b1));
}

// ---------------- prep: repack coeffs (2,I,O,G) f32 -> Wt[o][k] fp16 ----------------
__global__ void fkan_prep(const float* __restrict__ cf) {
    int idx = blockIdx.x * blockDim.x + threadIdx.x;
    if (idx >= NO * KTOT) return;
    int o = idx >> 13;
    int k = idx & (KTOT - 1);
    int i = k >> 4;
    int f = k & 15;
    int t = f >> 3;               // 0 = cos, 1 = sin
    int g = f & 7;                // freq-1
    float v = cf[(((t * NI) + i) * NO + o) * NG + g];
    g_Wt[o * KTOT + k] = __float2half(v);
}

// ---------------- main fused kernel ----------------
__global__ void __launch_bounds__(NTHREADS, 1)
fkan_main(const float* __restrict__ x, const float* __restrict__ bias,
          float* __restrict__ out) {
    extern __shared__ __align__(1024) char smem[];
    const uint32_t sbase = smem_u32(smem);

    const int tid = threadIdx.x;
    const int w = tid >> 5;
    const int lane = tid & 31;
    const int ctaRow = blockIdx.x * MCTA;

    // barriers: full[s] at s*16, empty[s] at s*16+8
    if (tid == 0) {
        #pragma unroll
        for (int s = 0; s < STAGES; ++s) {
            MBAR_INIT(sbase + s * 16, 224);       // full: 224 producer threads
            MBAR_INIT(sbase + s * 16 + 8, 224);   // empty: 224 consumer threads
        }
    }
    __syncthreads();

    if (w < 7) {
        // ================= CONSUMER: MMA warps =================
        const int mw = w;                   // rows mw*32 .. +31
        const uint32_t a_ls0 = SW128((uint32_t)((mw * 32 + (lane & 15)) * 128 +
                                                ((lane >> 4) << 4)));
        const uint32_t a_ls1 = SW128((uint32_t)((mw * 32 + 16 + (lane & 15)) * 128 +
                                                ((lane >> 4) << 4)));
        const uint32_t bl = (uint32_t)((lane & 7) + ((lane >> 4) << 3));
        const uint32_t bbo = (uint32_t)(((lane >> 3) & 1) << 4);
        uint32_t b_ls[4];
        #pragma unroll
        for (int t = 0; t < 4; ++t)
            b_ls[t] = SW128((uint32_t)((t * 16 + bl) * 128 + bbo));

        float acc[2][8][4];
        #pragma unroll
        for (int mi = 0; mi < 2; ++mi)
            #pragma unroll
            for (int j = 0; j < 8; ++j)
                #pragma unroll
                for (int q = 0; q < 4; ++q) acc[mi][j][q] = 0.0f;

        int s = 0, mpar = 0;
        #pragma unroll 1
        for (int c = 0; c < NCHUNK; ++c) {
            MBAR_WAIT_PARITY(sbase + s * 16, mpar);            // wait full[s]
            const uint32_t aB = sbase + SMEM_BUF0 + (uint32_t)s * BUFSZ;
            const uint32_t bB = aB + ABYTES;

            #pragma unroll
            for (int ks = 0; ks < 4; ++ks) {
                const uint32_t kx = (uint32_t)(ks << 5);
                uint32_t a0[4], a1[4], b[16];
                LDSM_X4(a0[0], a0[1], a0[2], a0[3], aB + (a_ls0 ^ kx));
                LDSM_X4(a1[0], a1[1], a1[2], a1[3], aB + (a_ls1 ^ kx));
                #pragma unroll
                for (int t = 0; t < 4; ++t)
                    LDSM_X4(b[4 * t], b[4 * t + 1], b[4 * t + 2], b[4 * t + 3],
                            bB + (b_ls[t] ^ kx));
                #pragma unroll
                for (int j = 0; j < 8; ++j) {
                    const int t = j >> 1;
                    const int hi = (j & 1) << 1;
                    mma16816(acc[0][j], a0, b[4 * t + hi], b[4 * t + hi + 1]);
                    mma16816(acc[1][j], a1, b[4 * t + hi], b[4 * t + hi + 1]);
                }
            }

            MBAR_ARRIVE(sbase + s * 16 + 8);                   // arrive empty[s]
            if (++s == STAGES) { s = 0; mpar ^= 1; }
        }

        // ---- epilogue: acc (+bias) -> out, predicated for the tail CTA ----
        const int gr = lane >> 2;
        const int gc = (lane & 3) << 1;
        #pragma unroll
        for (int mi = 0; mi < 2; ++mi) {
            const int row0 = ctaRow + mw * 32 + mi * 16 + gr;
            #pragma unroll
            for (int j = 0; j < 8; ++j) {
                const int col = j * 8 + gc;
                float2 bb2 = *(const float2*)(bias + col);
                float2 v0, v1;
                v0.x = acc[mi][j][0] + bb2.x; v0.y = acc[mi][j][1] + bb2.y;
                v1.x = acc[mi][j][2] + bb2.x; v1.y = acc[mi][j][3] + bb2.y;
                if (row0 < NB)
                    *(float2*)(out + (size_t)row0 * NO + col) = v0;
                if (row0 + 8 < NB)
                    *(float2*)(out + (size_t)(row0 + 8) * NO + col) = v1;
            }
        }
    } else {
        // ================= PRODUCER: feature warps =================
        const int p = tid - 224;            // 0..223
        const int row = p;                  // one full row (4 i-units) per thread
        const int grow = ctaRow + row;
        const int crow = (grow < NB) ? grow : (NB - 1);    // clamp for tail CTA
        const float* xrow = x + (size_t)crow * NI;
        uint32_t fst[8];
        #pragma unroll
        for (int j = 0; j < 4; ++j) {
            fst[2 * j]     = SW128((uint32_t)(row * 128 + j * 32));
            fst[2 * j + 1] = SW128((uint32_t)(row * 128 + j * 32 + 16));
        }
        // B loader: threads p<128 handle it; bo = p>>1 (0..63), 4 x 16B units
        const bool doB = (p < 128);
        const int bo = p >> 1;
        const int buh = (p & 1) << 2;
        const __half* wsrc = g_Wt + bo * KTOT + buh * 8;
        uint32_t b_st[4];
        #pragma unroll
        for (int u = 0; u < 4; ++u)
            b_st[u] = SW128((uint32_t)(bo * 128 + (buh + u) * 16));

        float4 xv = *(const float4*)(xrow);      // chunk 0

        int s = 0, mpar = 0;
        #pragma unroll 1
        for (int c = 0; c < NCHUNK; ++c) {
            // prefetch next chunk's x (clamped)
            const int cp = (c + 1 < NCHUNK) ? c + 1 : NCHUNK - 1;
            float4 xn = *(const float4*)(xrow + cp * 4);

            MBAR_WAIT_PARITY(sbase + s * 16 + 8, mpar ^ 1);    // wait empty[s]
            const uint32_t aB = sbase + SMEM_BUF0 + (uint32_t)s * BUFSZ;
            const uint32_t bB = aB + ABYTES;

            // B tile via cp.async
            if (doB) {
                #pragma unroll
                for (int u = 0; u < 4; ++u)
                    CP_ASYNC16(bB + b_st[u], wsrc + (size_t)c * KC + u * 8);
            }
            CP_COMMIT();

            // A features: 4 i-units for this row
            const float xs[4] = {xv.x, xv.y, xv.z, xv.w};
            #pragma unroll
            for (int j = 0; j < 4; ++j) {
                float s1, c1;
                __sincosf(xs[j], &s1, &c1);
                float t2 = c1 + c1;
                float ck[8], sk[8];
                ck[0] = c1; sk[0] = s1;
                float cm2 = 1.0f, sm2 = 0.0f;
                #pragma unroll
                for (int k = 1; k < 8; ++k) {
                    float cn = fmaf(t2, ck[k - 1], -cm2);
                    float sn = fmaf(t2, sk[k - 1], -sm2);
                    cm2 = ck[k - 1]; sm2 = sk[k - 1];
                    ck[k] = cn; sk[k] = sn;
                }
                __half2 h[8];
                h[0] = __floats2half2_rn(ck[0], ck[1]);
                h[1] = __floats2half2_rn(ck[2], ck[3]);
                h[2] = __floats2half2_rn(ck[4], ck[5]);
                h[3] = __floats2half2_rn(ck[6], ck[7]);
                h[4] = __floats2half2_rn(sk[0], sk[1]);
                h[5] = __floats2half2_rn(sk[2], sk[3]);
                h[6] = __floats2half2_rn(sk[4], sk[5]);
                h[7] = __floats2half2_rn(sk[6], sk[7]);
                uint4 vc, vs;
                vc.x = *(uint32_t*)&h[0]; vc.y = *(uint32_t*)&h[1];
                vc.z = *(uint32_t*)&h[2]; vc.w = *(uint32_t*)&h[3];
                vs.x = *(uint32_t*)&h[4]; vs.y = *(uint32_t*)&h[5];
                vs.z = *(uint32_t*)&h[6]; vs.w = *(uint32_t*)&h[7];
                *(uint4*)(smem + (aB - sbase) + fst[2 * j]) = vc;
                *(uint4*)(smem + (aB - sbase) + fst[2 * j + 1]) = vs;
            }

            CP_WAIT0();                        // B copies done (this thread)
            MBAR_ARRIVE(sbase + s * 16);       // arrive full[s]

            xv = xn;
            if (++s == STAGES) { s = 0; mpar ^= 1; }
        }
    }
}

// ---------------- launch ----------------
extern "C" void kernel_launch(void* const* d_in, const int* in_sizes, int n_in,
                              void* d_out, int out_size) {
    const float* x    = (const float*)d_in[0];
    const float* cf   = (const float*)d_in[1];
    const float* bias = (const float*)d_in[2];
    float* out        = (float*)d_out;

    static bool attr_set = false;
    if (!attr_set) {
        cudaFuncSetAttribute(fkan_main, cudaFuncAttributeMaxDynamicSharedMemorySize,
                             SMEM_TOTAL);
        attr_set = true;
    }

    fkan_prep<<<(NO * KTOT + 255) / 256, 256>>>(cf);
    fkan_main<<<NGRID, NTHREADS, SMEM_TOTAL>>>(x, bias, out);
}